// round 3
// baseline (speedup 1.0000x reference)
#include <cuda_runtime.h>
#include <math.h>
#include <complex>

#ifndef M_PI
#define M_PI 3.14159265358979323846
#endif

#define NB 32
#define NT 300
#define NC 3
#define HW 5184        // 72*72
#define TS 270         // NT - 30
#define WW 29          // window length - 1
#define PAD 18
#define EXT (NT + 2 * PAD)   // 336

struct FiltParams {
    float l1[NT];    // LDL^T: L[i,i-1] (unit lower)
    float l2[NT];    // LDL^T: L[i,i-2]
    float invd[NT];  // 1/D[i]
    float fb[6];     // butter numerator
    float fa[6];     // butter denominator (fa[0]=1)
};

// ---------------- scratch (static device globals; no allocation) ----------------
__device__ float g_m[NB * NT * NC];
__device__ float g_Pn[NB * TS * 32];   // w padded 29->32

// ---------------- helpers ----------------
__device__ __forceinline__ float wsum(float v) {
#pragma unroll
    for (int o = 16; o; o >>= 1) v += __shfl_xor_sync(0xffffffffu, v, o);
    return v;
}

// ---------------- kernel 1: spatial mean over 72x72 per (b,t,c) ----------------
__global__ void k_mean(const float* __restrict__ x) {
    int s = blockIdx.x;  // 0 .. NB*NT*NC-1, c fastest
    const float4* p = reinterpret_cast<const float4*>(x) + (size_t)s * (HW / 4);
    float acc = 0.f;
    for (int i = threadIdx.x; i < HW / 4; i += blockDim.x) {
        float4 v = p[i];
        acc += (v.x + v.y) + (v.z + v.w);
    }
    acc = wsum(acc);
    __shared__ float sh[8];
    int lane = threadIdx.x & 31, wid = threadIdx.x >> 5;
    if (lane == 0) sh[wid] = acc;
    __syncthreads();
    if (threadIdx.x < 8) {
        float v = sh[threadIdx.x];
#pragma unroll
        for (int o = 4; o; o >>= 1) v += __shfl_xor_sync(0xffu, v, o);
        if (threadIdx.x == 0) g_m[s] = v * (1.f / (float)HW);
    }
}

// ---------------- kernel 2: POS per-window -> Pn ----------------
__global__ void k_pos() {
    int gw = (blockIdx.x * blockDim.x + threadIdx.x) >> 5;  // one warp per (b,t)
    int lane = threadIdx.x & 31;
    if (gw >= NB * TS) return;
    int b = gw / TS, t = gw - b * TS;

    bool act = lane < WW;
    float c0 = 0.f, c1 = 0.f, c2 = 0.f;
    if (act) {
        const float* p = g_m + ((b * NT) + (t + lane)) * NC;
        c0 = p[0]; c1 = p[1]; c2 = p[2];
    }
    const float invw = 1.0f / (float)WW;
    float mu0 = wsum(c0) * invw;
    float mu1 = wsum(c1) * invw;
    float mu2 = wsum(c2) * invw;
    float n0 = c0 / mu0, n1 = c1 / mu1, n2 = c2 / mu2;
    float s0 = act ? (n1 - n2) : 0.f;
    float s1 = act ? (n1 + n2 - 2.f * n0) : 0.f;
    float m0 = wsum(s0) * invw;
    float m1 = wsum(s1) * invw;
    float d0 = act ? (s0 - m0) : 0.f;
    float d1 = act ? (s1 - m1) : 0.f;
    float v0 = wsum(d0 * d0) * invw;
    float v1 = wsum(d1 * d1) * invw;
    float alpha = sqrtf(v0) / sqrtf(v1);
    float P = s0 + alpha * s1;  // valid for act lanes
    float mp = wsum(act ? P : 0.f) * invw;
    float dp = act ? (P - mp) : 0.f;
    float vp = wsum(dp * dp) * invw;
    float pn = dp / sqrtf(vp);
    g_Pn[gw * 32 + lane] = act ? pn : 0.f;
}

// ---------------- kernel 3: Hs gather + detrend + filtfilt + minmax -------------
__device__ __forceinline__ double A_diag(int i) {
    double dd = (i == 0 || i == NT - 1) ? 1.0 : ((i == 1 || i == NT - 2) ? 5.0 : 6.0);
    return 1.0 + 10000.0 * dd;
}
__device__ __forceinline__ double A_e(int i) {  // A[i][i-1], valid for i>=1
    return 10000.0 * ((i == 1 || i == NT - 1) ? -2.0 : -4.0);
}

__global__ void __launch_bounds__(32) k_post(float* __restrict__ out, FiltParams P) {
    __shared__ float  sh_h[NT];
    __shared__ float  sh_t[NT];    // residual / z / zz / c scratch
    __shared__ float  sh_df[NT];
    __shared__ float  sh_c[EXT];   // FIR part scratch
    __shared__ float  sh_y1[EXT];
    __shared__ float  sh_f[NT];
    __shared__ double sh_y[NT];

    const int b = blockIdx.x;
    const int lane = threadIdx.x;

    // ---- overlap-add gather: Hs[tau] = sum_t Pn[b,t,tau-t] -----------------------
    for (int tau = lane; tau < NT; tau += 32) {
        int tlo = tau - (WW - 1); if (tlo < 0) tlo = 0;
        int thi = tau; if (thi > TS - 1) thi = TS - 1;
        float s = 0.f;
        for (int t = tlo; t <= thi; t++) s += g_Pn[(b * TS + t) * 32 + (tau - t)];
        sh_h[tau] = s;
        sh_y[tau] = 0.0;
    }
    __syncwarp();

    // ---- iterative refinement: LDL^T float sweeps + fp64 residual ---------------
    for (int it = 0; it < 3; it++) {
        // residual r = h - A y  (fp64, parallel across lanes)
        for (int i = lane; i < NT; i += 32) {
            double acc = (double)sh_h[i];
            acc -= A_diag(i) * sh_y[i];
            if (i >= 1)      acc -= A_e(i) * sh_y[i - 1];
            if (i <= NT - 2) acc -= A_e(i + 1) * sh_y[i + 1];
            if (i >= 2)      acc -= 10000.0 * sh_y[i - 2];
            if (i <= NT - 3) acc -= 10000.0 * sh_y[i + 2];
            sh_t[i] = (float)acc;
        }
        __syncwarp();
        // forward: L z = r  (unit lower, chain = 1 FFMA/step)
        if (lane == 0) {
            float z2 = sh_t[0];
            float z1 = fmaf(-P.l1[1], z2, sh_t[1]);
            sh_t[1] = z1;
#pragma unroll 4
            for (int i = 2; i < NT; i++) {
                float s = fmaf(-P.l2[i], z2, sh_t[i]);
                float z = fmaf(-P.l1[i], z1, s);
                sh_t[i] = z; z2 = z1; z1 = z;
            }
        }
        __syncwarp();
        // diagonal scale (parallel)
        for (int i = lane; i < NT; i += 32) sh_t[i] *= P.invd[i];
        __syncwarp();
        // backward: L^T c = zz  (chain = 1 FFMA/step)
        if (lane == 0) {
            float c1 = sh_t[NT - 1];
            float c0 = fmaf(-P.l1[NT - 1], c1, sh_t[NT - 2]);
            sh_t[NT - 2] = c0;
#pragma unroll 4
            for (int i = NT - 3; i >= 0; i--) {
                float s = fmaf(-P.l2[i + 2], c1, sh_t[i]);
                float c = fmaf(-P.l1[i + 1], c0, s);
                sh_t[i] = c; c1 = c0; c0 = c;
            }
        }
        __syncwarp();
        for (int i = lane; i < NT; i += 32) sh_y[i] += (double)sh_t[i];
        __syncwarp();
    }

    // detrended signal
    for (int i = lane; i < NT; i += 32) sh_df[i] = sh_h[i] - (float)sh_y[i];
    __syncwarp();

    // ---- filtfilt ---------------------------------------------------------------
    // Build extended signal into sh_y1 (reuse as ext buffer first)
    for (int j = lane; j < EXT; j += 32) {
        float v;
        if (j < PAD)            v = 2.f * sh_df[0] - sh_df[PAD - j];
        else if (j < PAD + NT)  v = sh_df[j - PAD];
        else                    v = 2.f * sh_df[NT - 1] - sh_df[NT - 2 - (j - PAD - NT)];
        sh_c[j] = v;   // sh_c temporarily holds ext input
    }
    __syncwarp();
    float x0 = sh_c[0];
    // FIR part c[j] = sum_k fb[k] * ext[j-k]  (virtual ext[<0] = x0), parallel
    for (int j = lane; j < EXT; j += 32) {
        float acc = 0.f;
#pragma unroll
        for (int k = 0; k < 6; k++) {
            float xv = (j >= k) ? sh_c[j - k] : x0;
            acc = fmaf(P.fb[k], xv, acc);
        }
        sh_y1[j] = acc;   // sh_y1 temporarily holds FIR part
    }
    __syncwarp();
    // feedback pass 1 (lane 0): y[j] = c[j] - sum a_k y[j-k], virtual y[<0] = x0
    if (lane == 0) {
        float p1 = x0, p2 = x0, p3 = x0, p4 = x0, p5 = x0;
        const float a1 = P.fa[1], a2 = P.fa[2], a3 = P.fa[3], a4 = P.fa[4], a5 = P.fa[5];
#pragma unroll 4
        for (int j = 0; j < EXT; j++) {
            float t = fmaf(-a5, p5, sh_y1[j]);
            t = fmaf(-a4, p4, t);
            t = fmaf(-a3, p3, t);
            t = fmaf(-a2, p2, t);
            float yv = fmaf(-a1, p1, t);
            sh_c[j] = yv;   // sh_c now holds y1 (pass-1 output)
            p5 = p4; p4 = p3; p3 = p2; p2 = p1; p1 = yv;
        }
    }
    __syncwarp();
    float x0b = sh_c[EXT - 1];
    // FIR part of pass 2 over reversed y1, parallel
    for (int j = lane; j < EXT; j += 32) {
        float acc = 0.f;
#pragma unroll
        for (int k = 0; k < 6; k++) {
            float xv = (j >= k) ? sh_c[EXT - 1 - j + k] : x0b;
            acc = fmaf(P.fb[k], xv, acc);
        }
        sh_y1[j] = acc;
    }
    __syncwarp();
    // feedback pass 2 (lane 0), keep trimmed reversed output f[i] = y2r[(PAD+NT-1)-...]
    if (lane == 0) {
        float p1 = x0b, p2 = x0b, p3 = x0b, p4 = x0b, p5 = x0b;
        const float a1 = P.fa[1], a2 = P.fa[2], a3 = P.fa[3], a4 = P.fa[4], a5 = P.fa[5];
#pragma unroll 4
        for (int j = 0; j < EXT; j++) {
            float t = fmaf(-a5, p5, sh_y1[j]);
            t = fmaf(-a4, p4, t);
            t = fmaf(-a3, p3, t);
            t = fmaf(-a2, p2, t);
            float yv = fmaf(-a1, p1, t);
            int i = (PAD + NT - 1) - j;
            if (i >= 0 && i < NT) sh_f[i] = yv;
            p5 = p4; p4 = p3; p3 = p2; p2 = p1; p1 = yv;
        }
    }
    __syncwarp();

    // ---- min/max (parallel) + normalize ----------------------------------------
    float mn = 3.0e38f, mx = -3.0e38f;
    for (int i = lane; i < NT; i += 32) {
        float v = sh_f[i];
        mn = fminf(mn, v); mx = fmaxf(mx, v);
    }
#pragma unroll
    for (int o = 16; o; o >>= 1) {
        mn = fminf(mn, __shfl_xor_sync(0xffffffffu, mn, o));
        mx = fmaxf(mx, __shfl_xor_sync(0xffffffffu, mx, o));
    }
    float inv = 1.f / (mx - mn);
    for (int i = lane; i < NT; i += 32) out[b * NT + i] = (sh_f[i] - mn) * inv;
}

// ---------------- host-side constant computation (capture-time, deterministic) ---
static void compute_params(FiltParams& FP) {
    // banded LDL^T of A = I + lam^2 D^T D  (double)
    const double L2 = 10000.0;
    double dgl[NT], e1[NT];
    for (int i = 0; i < NT; i++) {
        double dd = (i == 0 || i == NT - 1) ? 1.0 : ((i == 1 || i == NT - 2) ? 5.0 : 6.0);
        dgl[i] = 1.0 + L2 * dd;
        e1[i]  = (i == 0) ? 0.0 : L2 * ((i == 1 || i == NT - 1) ? -2.0 : -4.0);
    }
    double d[NT], l1[NT], l2[NT];
    l1[0] = 0.0; l2[0] = 0.0; l2[1] = 0.0;
    d[0] = dgl[0];
    l1[1] = e1[1] / d[0];
    d[1] = dgl[1] - l1[1] * l1[1] * d[0];
    for (int i = 2; i < NT; i++) {
        l2[i] = L2 / d[i - 2];
        l1[i] = (e1[i] - l2[i] * l1[i - 1] * d[i - 2]) / d[i - 1];
        d[i] = dgl[i] - l1[i] * l1[i] * d[i - 1] - l2[i] * l2[i] * d[i - 2];
    }
    for (int i = 0; i < NT; i++) {
        FP.l1[i] = (float)l1[i];
        FP.l2[i] = (float)l2[i];
        FP.invd[i] = (float)(1.0 / d[i]);
    }

    // Butterworth order 5, wn = 0.2 (matches reference formulas, double precision)
    using cd = std::complex<double>;
    const int ORD = 5;
    double wn = 3.0 / 15.0;
    double warped = 4.0 * tan(M_PI * wn / 2.0);
    cd p[ORD];
    for (int k = 1; k <= ORD; k++) {
        double ang = M_PI * (2.0 * k + ORD - 1.0) / (2.0 * ORD);
        p[k - 1] = warped * std::exp(cd(0.0, ang));
    }
    double kg = pow(warped, (double)ORD);
    cd pz[ORD];
    cd prod(1.0, 0.0);
    for (int k = 0; k < ORD; k++) {
        pz[k] = (4.0 + p[k]) / (4.0 - p[k]);
        prod *= (4.0 - p[k]);
    }
    double kz = kg * std::real(1.0 / prod);
    const double binom[6] = {1, 5, 10, 10, 5, 1};
    double bcoef[6], acoef[6];
    for (int i = 0; i < 6; i++) bcoef[i] = kz * binom[i];
    // poly(pz), monic
    cd ac[6];
    ac[0] = cd(1.0, 0.0);
    for (int i = 1; i < 6; i++) ac[i] = cd(0.0, 0.0);
    for (int k = 0; k < ORD; k++)
        for (int j = k + 1; j >= 1; j--) ac[j] = ac[j] - pz[k] * ac[j - 1];
    for (int i = 0; i < 6; i++) acoef[i] = std::real(ac[i]);

    for (int i = 0; i < 6; i++) { FP.fb[i] = (float)bcoef[i]; FP.fa[i] = (float)acoef[i]; }
}

// ---------------- launch ----------------
extern "C" void kernel_launch(void* const* d_in, const int* in_sizes, int n_in,
                              void* d_out, int out_size) {
    const float* x = (const float*)d_in[0];
    float* out = (float*)d_out;

    FiltParams FP;
    compute_params(FP);

    k_mean<<<NB * NT * NC, 256>>>(x);
    k_pos<<<(NB * TS * 32 + 127) / 128, 128>>>();
    k_post<<<NB, 32>>>(out, FP);
}

// round 5
// speedup vs baseline: 1.0354x; 1.0354x over previous
#include <cuda_runtime.h>
#include <math.h>
#include <complex>

#ifndef M_PI
#define M_PI 3.14159265358979323846
#endif

#define NB 32
#define NT 300
#define NC 3
#define HW 5184        // 72*72
#define TS 270         // NT - 30
#define WW 29          // window length - 1
#define PAD 18
#define EXT (NT + 2 * PAD)   // 336

struct FiltParams {
    float l1[NT];    // LDL^T: L[i,i-1] (unit lower)
    float l2[NT];    // LDL^T: L[i,i-2]
    float invd[NT];  // 1/D[i]
    float fb[6];     // butter numerator
    float fa[6];     // butter denominator (fa[0]=1)
};

// ---------------- scratch (static device globals; no allocation) ----------------
__device__ float g_m[NB * NT * NC];
__device__ float g_Pn[NB * TS * 32];   // w padded 29->32

// ---------------- helpers ----------------
__device__ __forceinline__ float wsum(float v) {
#pragma unroll
    for (int o = 16; o; o >>= 1) v += __shfl_xor_sync(0xffffffffu, v, o);
    return v;
}

// ---------------- kernel 1: spatial mean over 72x72 per (b,t,c) ----------------
__global__ void k_mean(const float* __restrict__ x) {
    int s = blockIdx.x;  // 0 .. NB*NT*NC-1, c fastest
    const float4* p = reinterpret_cast<const float4*>(x) + (size_t)s * (HW / 4);
    float acc = 0.f;
    for (int i = threadIdx.x; i < HW / 4; i += blockDim.x) {
        float4 v = p[i];
        acc += (v.x + v.y) + (v.z + v.w);
    }
    acc = wsum(acc);
    __shared__ float sh[8];
    int lane = threadIdx.x & 31, wid = threadIdx.x >> 5;
    if (lane == 0) sh[wid] = acc;
    __syncthreads();
    if (threadIdx.x < 8) {
        float v = sh[threadIdx.x];
#pragma unroll
        for (int o = 4; o; o >>= 1) v += __shfl_xor_sync(0xffu, v, o);
        if (threadIdx.x == 0) g_m[s] = v * (1.f / (float)HW);
    }
}

// ---------------- kernel 2: POS per-window -> Pn ----------------
__global__ void k_pos() {
    int gw = (blockIdx.x * blockDim.x + threadIdx.x) >> 5;  // one warp per (b,t)
    int lane = threadIdx.x & 31;
    if (gw >= NB * TS) return;
    int b = gw / TS, t = gw - b * TS;

    bool act = lane < WW;
    float c0 = 0.f, c1 = 0.f, c2 = 0.f;
    if (act) {
        const float* p = g_m + ((b * NT) + (t + lane)) * NC;
        c0 = p[0]; c1 = p[1]; c2 = p[2];
    }
    const float invw = 1.0f / (float)WW;
    float mu0 = wsum(c0) * invw;
    float mu1 = wsum(c1) * invw;
    float mu2 = wsum(c2) * invw;
    float n0 = c0 / mu0, n1 = c1 / mu1, n2 = c2 / mu2;
    float s0 = act ? (n1 - n2) : 0.f;
    float s1 = act ? (n1 + n2 - 2.f * n0) : 0.f;
    float m0 = wsum(s0) * invw;
    float m1 = wsum(s1) * invw;
    float d0 = act ? (s0 - m0) : 0.f;
    float d1 = act ? (s1 - m1) : 0.f;
    float v0 = wsum(d0 * d0) * invw;
    float v1 = wsum(d1 * d1) * invw;
    float alpha = sqrtf(v0) / sqrtf(v1);
    float P = s0 + alpha * s1;  // valid for act lanes
    float mp = wsum(act ? P : 0.f) * invw;
    float dp = act ? (P - mp) : 0.f;
    float vp = wsum(dp * dp) * invw;
    float pn = dp / sqrtf(vp);
    g_Pn[gw * 32 + lane] = act ? pn : 0.f;
}

// ---------------- kernel 3: Hs gather + detrend + filtfilt + minmax -------------
// A entries are exactly representable in float
__device__ __forceinline__ float A_diag_f(int i) {
    return (i == 0 || i == NT - 1) ? 10001.f : ((i == 1 || i == NT - 2) ? 50001.f : 60001.f);
}
__device__ __forceinline__ float A_e_f(int i) {  // A[i][i-1], valid for i>=1
    return (i == 1 || i == NT - 1) ? -20000.f : -40000.f;
}

// float-float accumulator helpers (Knuth twoSum, FMA twoProd)
struct FF { float hi, lo; };
__device__ __forceinline__ void ff_add_prod(FF& s, float a, float bh, float bl) {
    // s += a * (bh + bl), a and products tracked error-free
    float p = a * bh;
    float e = fmaf(a, bh, -p);          // exact product error
    float t = s.hi + p;
    float bb = t - s.hi;
    float err = (s.hi - (t - bb)) + (p - bb);
    s.hi = t;
    s.lo += err + e + a * bl;
}
__device__ __forceinline__ void ff_add(FF& s, float c) {
    float t = s.hi + c;
    float bb = t - s.hi;
    float err = (s.hi - (t - bb)) + (c - bb);
    s.hi = t;
    s.lo += err;
}

__global__ void __launch_bounds__(32) k_post(float* __restrict__ out, FiltParams P) {
    __shared__ float sh_h[NT];
    __shared__ float sh_t[NT];    // residual / z / c scratch
    __shared__ float sh_c[EXT];   // ext signal / pass-1 output
    __shared__ float sh_y1[EXT];  // FIR scratch
    __shared__ float sh_f[NT];
    __shared__ float sh_yh[NT];   // solution y (float-float)
    __shared__ float sh_yl[NT];
    __shared__ float sl1[NT], sl2[NT], sid[NT];  // coeffs staged in smem (LDS not LDC)

    const int b = blockIdx.x;
    const int lane = threadIdx.x;

    // stage coefficients + overlap-add gather
    for (int i = lane; i < NT; i += 32) {
        sl1[i] = P.l1[i]; sl2[i] = P.l2[i]; sid[i] = P.invd[i];
        int tau = i;
        int tlo = tau - (WW - 1); if (tlo < 0) tlo = 0;
        int thi = tau; if (thi > TS - 1) thi = TS - 1;
        float s = 0.f;
        for (int t = tlo; t <= thi; t++) s += g_Pn[(b * TS + t) * 32 + (tau - t)];
        sh_h[i] = s;
        sh_yh[i] = 0.f;
        sh_yl[i] = 0.f;
    }
    __syncwarp();

    // ---- iterative refinement: LDL^T float sweeps + float-float residual --------
    for (int it = 0; it < 3; it++) {
        // residual r = h - A y   (double-float, parallel across lanes)
        for (int i = lane; i < NT; i += 32) {
            FF s; s.hi = sh_h[i]; s.lo = 0.f;
            ff_add_prod(s, -A_diag_f(i), sh_yh[i], sh_yl[i]);
            if (i >= 1)      ff_add_prod(s, -A_e_f(i),     sh_yh[i - 1], sh_yl[i - 1]);
            if (i <= NT - 2) ff_add_prod(s, -A_e_f(i + 1), sh_yh[i + 1], sh_yl[i + 1]);
            if (i >= 2)      ff_add_prod(s, -10000.f,      sh_yh[i - 2], sh_yl[i - 2]);
            if (i <= NT - 3) ff_add_prod(s, -10000.f,      sh_yh[i + 2], sh_yl[i + 2]);
            sh_t[i] = s.hi + s.lo;
        }
        __syncwarp();
        // forward: L z = r  (unit lower, chain = 1 FFMA/step)
        if (lane == 0) {
            float z2 = sh_t[0];
            float z1 = fmaf(-sl1[1], z2, sh_t[1]);
            sh_t[1] = z1;
#pragma unroll 4
            for (int i = 2; i < NT; i++) {
                float s = fmaf(-sl2[i], z2, sh_t[i]);
                float z = fmaf(-sl1[i], z1, s);
                sh_t[i] = z; z2 = z1; z1 = z;
            }
        }
        __syncwarp();
        // diagonal scale (parallel)
        for (int i = lane; i < NT; i += 32) sh_t[i] *= sid[i];
        __syncwarp();
        // backward: L^T c = zz  (chain = 1 FFMA/step)
        if (lane == 0) {
            float c1 = sh_t[NT - 1];
            float c0 = fmaf(-sl1[NT - 1], c1, sh_t[NT - 2]);
            sh_t[NT - 2] = c0;
#pragma unroll 4
            for (int i = NT - 3; i >= 0; i--) {
                float s = fmaf(-sl2[i + 2], c1, sh_t[i]);
                float c = fmaf(-sl1[i + 1], c0, s);
                sh_t[i] = c; c1 = c0; c0 = c;
            }
        }
        __syncwarp();
        // y += c (float-float accumulate)
        for (int i = lane; i < NT; i += 32) {
            FF y; y.hi = sh_yh[i]; y.lo = sh_yl[i];
            ff_add(y, sh_t[i]);
            // quick renormalize
            float nh = y.hi + y.lo;
            float nl = y.lo - (nh - y.hi);
            sh_yh[i] = nh; sh_yl[i] = nl;
        }
        __syncwarp();
    }

    // detrended signal: d = h - y   (h - yh exact-ish via cancellation, then - yl)
    for (int i = lane; i < NT; i += 32) sh_h[i] = (sh_h[i] - sh_yh[i]) - sh_yl[i];
    __syncwarp();

    // ---- filtfilt ---------------------------------------------------------------
    // Build extended signal
    for (int j = lane; j < EXT; j += 32) {
        float v;
        if (j < PAD)            v = 2.f * sh_h[0] - sh_h[PAD - j];
        else if (j < PAD + NT)  v = sh_h[j - PAD];
        else                    v = 2.f * sh_h[NT - 1] - sh_h[NT - 2 - (j - PAD - NT)];
        sh_c[j] = v;   // sh_c temporarily holds ext input
    }
    __syncwarp();
    float x0 = sh_c[0];
    // FIR part c[j] = sum_k fb[k] * ext[j-k]  (virtual ext[<0] = x0), parallel
    for (int j = lane; j < EXT; j += 32) {
        float acc = 0.f;
#pragma unroll
        for (int k = 0; k < 6; k++) {
            float xv = (j >= k) ? sh_c[j - k] : x0;
            acc = fmaf(P.fb[k], xv, acc);
        }
        sh_y1[j] = acc;
    }
    __syncwarp();
    // feedback pass 1 (lane 0): y[j] = c[j] - sum a_k y[j-k], virtual y[<0] = x0
    if (lane == 0) {
        float p1 = x0, p2 = x0, p3 = x0, p4 = x0, p5 = x0;
        const float a1 = P.fa[1], a2 = P.fa[2], a3 = P.fa[3], a4 = P.fa[4], a5 = P.fa[5];
#pragma unroll 4
        for (int j = 0; j < EXT; j++) {
            float t = fmaf(-a5, p5, sh_y1[j]);
            t = fmaf(-a4, p4, t);
            t = fmaf(-a3, p3, t);
            t = fmaf(-a2, p2, t);
            float yv = fmaf(-a1, p1, t);
            sh_c[j] = yv;   // sh_c now holds pass-1 output
            p5 = p4; p4 = p3; p3 = p2; p2 = p1; p1 = yv;
        }
    }
    __syncwarp();
    float x0b = sh_c[EXT - 1];
    // FIR part of pass 2 over reversed y1, parallel
    for (int j = lane; j < EXT; j += 32) {
        float acc = 0.f;
#pragma unroll
        for (int k = 0; k < 6; k++) {
            float xv = (j >= k) ? sh_c[EXT - 1 - j + k] : x0b;
            acc = fmaf(P.fb[k], xv, acc);
        }
        sh_y1[j] = acc;
    }
    __syncwarp();
    // feedback pass 2 (lane 0), keep trimmed reversed output
    if (lane == 0) {
        float p1 = x0b, p2 = x0b, p3 = x0b, p4 = x0b, p5 = x0b;
        const float a1 = P.fa[1], a2 = P.fa[2], a3 = P.fa[3], a4 = P.fa[4], a5 = P.fa[5];
#pragma unroll 4
        for (int j = 0; j < EXT; j++) {
            float t = fmaf(-a5, p5, sh_y1[j]);
            t = fmaf(-a4, p4, t);
            t = fmaf(-a3, p3, t);
            t = fmaf(-a2, p2, t);
            float yv = fmaf(-a1, p1, t);
            int i = (PAD + NT - 1) - j;
            if (i >= 0 && i < NT) sh_f[i] = yv;
            p5 = p4; p4 = p3; p3 = p2; p2 = p1; p1 = yv;
        }
    }
    __syncwarp();

    // ---- min/max (parallel) + normalize ----------------------------------------
    float mn = 3.0e38f, mx = -3.0e38f;
    for (int i = lane; i < NT; i += 32) {
        float v = sh_f[i];
        mn = fminf(mn, v); mx = fmaxf(mx, v);
    }
#pragma unroll
    for (int o = 16; o; o >>= 1) {
        mn = fminf(mn, __shfl_xor_sync(0xffffffffu, mn, o));
        mx = fmaxf(mx, __shfl_xor_sync(0xffffffffu, mx, o));
    }
    float inv = 1.f / (mx - mn);
    for (int i = lane; i < NT; i += 32) out[b * NT + i] = (sh_f[i] - mn) * inv;
}

// ---------------- host-side constant computation (capture-time, deterministic) ---
static void compute_params(FiltParams& FP) {
    // banded LDL^T of A = I + lam^2 D^T D  (double)
    const double L2 = 10000.0;
    double dgl[NT], e1[NT];
    for (int i = 0; i < NT; i++) {
        double dd = (i == 0 || i == NT - 1) ? 1.0 : ((i == 1 || i == NT - 2) ? 5.0 : 6.0);
        dgl[i] = 1.0 + L2 * dd;
        e1[i]  = (i == 0) ? 0.0 : L2 * ((i == 1 || i == NT - 1) ? -2.0 : -4.0);
    }
    double d[NT], l1[NT], l2[NT];
    l1[0] = 0.0; l2[0] = 0.0; l2[1] = 0.0;
    d[0] = dgl[0];
    l1[1] = e1[1] / d[0];
    d[1] = dgl[1] - l1[1] * l1[1] * d[0];
    for (int i = 2; i < NT; i++) {
        l2[i] = L2 / d[i - 2];
        l1[i] = (e1[i] - l2[i] * l1[i - 1] * d[i - 2]) / d[i - 1];
        d[i] = dgl[i] - l1[i] * l1[i] * d[i - 1] - l2[i] * l2[i] * d[i - 2];
    }
    for (int i = 0; i < NT; i++) {
        FP.l1[i] = (float)l1[i];
        FP.l2[i] = (float)l2[i];
        FP.invd[i] = (float)(1.0 / d[i]);
    }

    // Butterworth order 5, wn = 0.2 (matches reference formulas, double precision)
    using cd = std::complex<double>;
    const int ORD = 5;
    double wn = 3.0 / 15.0;
    double warped = 4.0 * tan(M_PI * wn / 2.0);
    cd p[ORD];
    for (int k = 1; k <= ORD; k++) {
        double ang = M_PI * (2.0 * k + ORD - 1.0) / (2.0 * ORD);
        p[k - 1] = warped * std::exp(cd(0.0, ang));
    }
    double kg = pow(warped, (double)ORD);
    cd pz[ORD];
    cd prod(1.0, 0.0);
    for (int k = 0; k < ORD; k++) {
        pz[k] = (4.0 + p[k]) / (4.0 - p[k]);
        prod *= (4.0 - p[k]);
    }
    double kz = kg * std::real(1.0 / prod);
    const double binom[6] = {1, 5, 10, 10, 5, 1};
    double bcoef[6], acoef[6];
    for (int i = 0; i < 6; i++) bcoef[i] = kz * binom[i];
    // poly(pz), monic
    cd ac[6];
    ac[0] = cd(1.0, 0.0);
    for (int i = 1; i < 6; i++) ac[i] = cd(0.0, 0.0);
    for (int k = 0; k < ORD; k++)
        for (int j = k + 1; j >= 1; j--) ac[j] = ac[j] - pz[k] * ac[j - 1];
    for (int i = 0; i < 6; i++) acoef[i] = std::real(ac[i]);

    for (int i = 0; i < 6; i++) { FP.fb[i] = (float)bcoef[i]; FP.fa[i] = (float)acoef[i]; }
}

// ---------------- launch ----------------
extern "C" void kernel_launch(void* const* d_in, const int* in_sizes, int n_in,
                              void* d_out, int out_size) {
    const float* x = (const float*)d_in[0];
    float* out = (float*)d_out;

    FiltParams FP;
    compute_params(FP);

    k_mean<<<NB * NT * NC, 256>>>(x);
    k_pos<<<(NB * TS * 32 + 127) / 128, 128>>>();
    k_post<<<NB, 32>>>(out, FP);
}